// round 14
// baseline (speedup 1.0000x reference)
#include <cuda_runtime.h>
#include <cuda_bf16.h>
#include <cuda_fp16.h>
#include <math.h>
#include <stdint.h>

#define VOCAB 50000
#define EMB   512
#define HID   1024
#define G4    4096   // 4*HID
#define TT    256
#define BB    256

// ---------------- device scratch ----------------
__device__ __half g_xg[(size_t)TT * BB * G4];         // [T][B][4H] input gates (+biases), fp16
__device__ __nv_bfloat16 g_hb[2][BB * HID];           // double-buffered hidden (bf16)
__device__ __nv_bfloat16 g_whh[(size_t)G4 * HID];     // bf16 w_hh
__device__ __nv_bfloat16 g_wih[(size_t)G4 * EMB];     // bf16 w_ih
__device__ __nv_bfloat16 g_emb[(size_t)VOCAB * EMB];  // bf16 embedding table
__device__ int   g_is64;
__device__ unsigned g_bar2[2];                        // per-batch-group barriers

// ---------------- helpers ----------------
__device__ __forceinline__ uint32_t smem_u32(const void* p) {
    uint32_t a;
    asm("{ .reg .u64 t; cvta.to.shared.u64 t, %1; cvt.u32.u64 %0, t; }" : "=r"(a) : "l"(p));
    return a;
}
__device__ __forceinline__ void cpasync16(uint32_t dst, const void* src) {
    asm volatile("cp.async.cg.shared.global [%0], [%1], 16;" :: "r"(dst), "l"(src));
}
#define CP_COMMIT()  asm volatile("cp.async.commit_group;" ::: "memory")
#define CP_WAIT(n)   asm volatile("cp.async.wait_group %0;" :: "n"(n) : "memory")

__device__ __forceinline__ void ldsm4(uint32_t& r0, uint32_t& r1, uint32_t& r2, uint32_t& r3,
                                      uint32_t addr) {
    asm volatile("ldmatrix.sync.aligned.m8n8.x4.shared.b16 {%0,%1,%2,%3}, [%4];"
                 : "=r"(r0), "=r"(r1), "=r"(r2), "=r"(r3) : "r"(addr));
}
__device__ __forceinline__ void mma_bf16(float4& d, const uint32_t a[4],
                                         uint32_t b0, uint32_t b1) {
    asm volatile("mma.sync.aligned.m16n8k16.row.col.f32.bf16.bf16.f32 "
        "{%0,%1,%2,%3}, {%4,%5,%6,%7}, {%8,%9}, {%0,%1,%2,%3};"
        : "+f"(d.x), "+f"(d.y), "+f"(d.z), "+f"(d.w)
        : "r"(a[0]), "r"(a[1]), "r"(a[2]), "r"(a[3]), "r"(b0), "r"(b1));
}

__device__ __forceinline__ float sigmoid_fast(float x) {
    return 1.f / (1.f + __expf(-x));
}
__device__ __forceinline__ float tanh_fast(float x) {
    x = fminf(fmaxf(x, -15.f), 15.f);
    float e = __expf(2.f * x);
    return (e - 1.f) / (e + 1.f);
}

// ---------------- prep kernels ----------------
__global__ void init_all(const void* text) {
    int i = blockIdx.x * blockDim.x + threadIdx.x;
    if (i == 0) {
        const long long* p = (const long long*)text;
        int ok = 1;
        for (int k = 0; k < 64; k++) {
            long long v = p[k];
            if (v < 0 || v >= VOCAB) ok = 0;
        }
        g_is64 = ok;
        g_bar2[0] = 0u;
        g_bar2[1] = 0u;
    }
    if (i < BB * HID) {
        g_hb[0][i] = __float2bfloat16(0.f);
        g_hb[1][i] = __float2bfloat16(0.f);
    }
}

#define N4_WHH  ((size_t)G4 * HID / 4)
#define N4_WIH  ((size_t)G4 * EMB / 4)
#define N4_EMB  ((size_t)VOCAB * EMB / 4)
__global__ void conv_all(const float* __restrict__ whh,
                         const float* __restrict__ wih,
                         const float* __restrict__ emb)
{
    size_t i4 = (size_t)blockIdx.x * 256 + threadIdx.x;
    const float* src;
    __nv_bfloat16* dst;
    size_t k4;
    if (i4 < N4_WHH)                    { src = whh; dst = g_whh; k4 = i4; }
    else if (i4 < N4_WHH + N4_WIH)      { src = wih; dst = g_wih; k4 = i4 - N4_WHH; }
    else                                { src = emb; dst = g_emb; k4 = i4 - N4_WHH - N4_WIH; }
    size_t i = k4 * 4;
    float4 v = *(const float4*)(src + i);
    *(__nv_bfloat162*)(dst + i)     = __floats2bfloat162_rn(v.x, v.y);
    *(__nv_bfloat162*)(dst + i + 2) = __floats2bfloat162_rn(v.z, v.w);
}

// ---------------- bf16 MMA embedding gather + input GEMM (launch #3) ----------------
#define EPITCH 80
#define ESA0   0
#define ESA1   10240
#define ESB0   20480
#define ESB1   30720
#define ESEND  40960

__global__ __launch_bounds__(256) void embed_mma(
    const void* __restrict__ text,
    const float* __restrict__ b_ih,
    const float* __restrict__ b_hh)
{
    __shared__ __align__(16) char smem[ESEND];
    __shared__ int   toks[128];
    __shared__ float bias[128];
    const uint32_t sb = smem_u32(smem);

    const int tid  = threadIdx.x;
    const int lane = tid & 31;
    const int warp = tid >> 5;
    const int wm   = warp >> 1;
    const int wn   = warp & 1;
    const int m0 = blockIdx.x * 128;
    const int n0 = blockIdx.y * 128;

    if (tid < 128) {
        int m = m0 + tid;
        toks[tid] = g_is64 ? (int)((const long long*)text)[m]
                           : ((const int*)text)[m];
        bias[tid] = b_ih[n0 + tid] + b_hh[n0 + tid];
    }
    __syncthreads();

    auto issue = [&](int buf, int chunk) {
        const int k0 = chunk * 32;
#pragma unroll
        for (int l = 0; l < 2; l++) {
            int idx = l * 256 + tid;
            int r = idx >> 2, q = (idx & 3) << 3;
            cpasync16(sb + (buf ? ESA1 : ESA0) + r * EPITCH + q * 2,
                      g_emb + (size_t)toks[r] * EMB + k0 + q);
        }
#pragma unroll
        for (int l = 0; l < 2; l++) {
            int idx = l * 256 + tid;
            int r = idx >> 2, q = (idx & 3) << 3;
            cpasync16(sb + (buf ? ESB1 : ESB0) + r * EPITCH + q * 2,
                      g_wih + (size_t)(n0 + r) * EMB + k0 + q);
        }
        CP_COMMIT();
    };

    float4 acc[2][8];
#pragma unroll
    for (int i = 0; i < 2; i++)
#pragma unroll
        for (int j = 0; j < 8; j++) acc[i][j] = make_float4(0.f, 0.f, 0.f, 0.f);

    issue(0, 0);
    issue(1, 1);

    const uint32_t laneoff = (uint32_t)((lane & 15) * EPITCH + (lane >> 4) * 16);

    for (int c = 0; c < 16; c++) {
        if (c < 15) CP_WAIT(1);
        else        CP_WAIT(0);
        __syncthreads();

        const uint32_t aB = sb + ((c & 1) ? ESA1 : ESA0);
        const uint32_t bB = sb + ((c & 1) ? ESB1 : ESB0);

#pragma unroll
        for (int ks = 0; ks < 2; ks++) {
            uint32_t a[2][4];
#pragma unroll
            for (int mi = 0; mi < 2; mi++) {
                uint32_t ad = aB + (uint32_t)((wm * 32 + mi * 16) * EPITCH + ks * 32) + laneoff;
                ldsm4(a[mi][0], a[mi][1], a[mi][2], a[mi][3], ad);
            }
#pragma unroll
            for (int nj = 0; nj < 4; nj++) {
                uint32_t f0, f1, f2, f3;
                uint32_t bd = bB + (uint32_t)((wn * 64 + nj * 16) * EPITCH + ks * 32) + laneoff;
                ldsm4(f0, f1, f2, f3, bd);
#pragma unroll
                for (int mi = 0; mi < 2; mi++) {
                    mma_bf16(acc[mi][nj * 2],     a[mi], f0, f2);
                    mma_bf16(acc[mi][nj * 2 + 1], a[mi], f1, f3);
                }
            }
        }
        __syncthreads();
        if (c + 2 < 16) issue(c & 1, c + 2);
    }

    const int gid = lane >> 2;
    const int tig = lane & 3;
#pragma unroll
    for (int mi = 0; mi < 2; mi++) {
        int R = wm * 32 + mi * 16 + gid;
        int mA = m0 + R;
        int mB = mA + 8;
        size_t baseA = ((size_t)(mA & 255) * BB + (mA >> 8)) * G4 + n0;
        size_t baseB = ((size_t)(mB & 255) * BB + (mB >> 8)) * G4 + n0;
#pragma unroll
        for (int nj = 0; nj < 4; nj++) {
#pragma unroll
            for (int h = 0; h < 2; h++) {
                float4 v = acc[mi][nj * 2 + h];
                int C = wn * 64 + nj * 16 + h * 8 + tig * 2;
                *(__half2*)(g_xg + baseA + C) =
                    __floats2half2_rn(v.x + bias[C], v.y + bias[C + 1]);
                *(__half2*)(g_xg + baseB + C) =
                    __floats2half2_rn(v.z + bias[C], v.w + bias[C + 1]);
            }
        }
    }
}

// ---------------- persistent recurrent kernel ----------------
// 256 threads, 8 warps (4M x 2N). B (64 x 1024 bf16) resident in smem.
// A: per-warp PRIVATE double-buffered 32-row slices filled with cp.async —
// no __syncthreads in the 16-chunk K loop (warp-order guarantees safety).
#define BM    128
#define BJ    16
#define BK2   64           // K chunk (16 chunks)
#define PAW   144          // private A row pitch (128B data + 16; 144%128==16 like 272)
#define PB    2064
#define SMB   0            // B resident: 64 * 2064 = 132096
#define ABASE 132096       // per-warp A buffers: 16 x (32*144=4608) = 73728
#define ABUF  4608
#define SMTOT 205824
#define GSP   68

__global__ __launch_bounds__(256, 1) void lstm_persist()
{
    extern __shared__ __align__(16) char smem[];
    const uint32_t sb = smem_u32(smem);

    const int tid  = threadIdx.x;
    const int lane = tid & 31;
    const int warp = tid >> 5;
    const int wm   = warp >> 1;          // 0..3 (A rows wm*32..+32)
    const int wn   = warp & 1;           // 0..1 (B rows wn*32..+32)
    const int cta  = blockIdx.x;
    const int grp  = cta >> 6;           // batch group 0/1
    const int b0   = grp * BM;
    const int j0   = (cta & 63) * BJ;

    // resident w_hh slice: 64 rows x 2048B
#pragma unroll
    for (int l = 0; l < 32; l++) {
        int idx = l * 256 + tid;
        int r = idx >> 7;
        int q = idx & 127;
        int grow = ((r >> 4) << 10) + j0 + (r & 15);
        cpasync16(sb + SMB + r * PB + q * 16, g_whh + (size_t)grow * HID + q * 8);
    }
    CP_COMMIT();
    CP_WAIT(0);
    __syncthreads();

    const uint32_t laneoffA = (uint32_t)((lane & 15) * PAW + (lane >> 4) * 16);
    const uint32_t laneoffB = (uint32_t)((lane & 15) * PB + (lane >> 4) * 16);
    const uint32_t abuf0 = sb + ABASE + (uint32_t)(warp * 2) * ABUF;
    const uint32_t abuf1 = abuf0 + ABUF;

    const int mrow = tid >> 4;           // 0..15 base row offset
    const int jj   = tid & 15;
    float cr[8];
#pragma unroll
    for (int l = 0; l < 8; l++) cr[l] = 0.f;
    float xr[8][4];

    auto pre_xg = [&](int t) {
        const __half* xb = g_xg + ((size_t)t * BB + b0) * G4 + j0 + jj;
#pragma unroll
        for (int l = 0; l < 8; l++) {
            const __half* p = xb + (size_t)(l * 16 + mrow) * G4;
            xr[l][0] = __half2float(p[0]);
            xr[l][1] = __half2float(p[1024]);
            xr[l][2] = __half2float(p[2048]);
            xr[l][3] = __half2float(p[3072]);
        }
    };
    pre_xg(0);

    unsigned* bp = &g_bar2[grp];

    for (int t = 0; t < TT; t++) {
        const __nv_bfloat16* hin = g_hb[t & 1];
        __nv_bfloat16* hout      = g_hb[(t + 1) & 1];

        // per-warp fill of this warp's 32 A rows, chunk = 64 K cols = 128B/row
        auto issueA = [&](int chunk) {
            const uint32_t dst = (chunk & 1) ? abuf1 : abuf0;
            const __nv_bfloat16* src =
                hin + (size_t)(b0 + wm * 32) * HID + chunk * BK2;
#pragma unroll
            for (int l = 0; l < 8; l++) {
                int idx = l * 32 + lane;   // 256 16B-chunks
                int r = idx >> 3, q = idx & 7;
                cpasync16(dst + r * PAW + q * 16, src + (size_t)r * HID + q * 8);
            }
            CP_COMMIT();
        };

        issueA(0);
        issueA(1);

        float4 acc[2][4];
#pragma unroll
        for (int i = 0; i < 2; i++)
#pragma unroll
            for (int j = 0; j < 4; j++) acc[i][j] = make_float4(0.f, 0.f, 0.f, 0.f);

        // 16 chunks, NO block barriers — each warp fully independent
        for (int c = 0; c < 16; c++) {
            if (c < 15) CP_WAIT(1);
            else        CP_WAIT(0);

            const uint32_t aB = (c & 1) ? abuf1 : abuf0;
            const uint32_t bB = sb + SMB + (uint32_t)(c * 128);

#pragma unroll
            for (int ks = 0; ks < 4; ks++) {
                uint32_t a[2][4];
#pragma unroll
                for (int mi = 0; mi < 2; mi++) {
                    uint32_t ad = aB + (uint32_t)((mi * 16) * PAW + ks * 32) + laneoffA;
                    ldsm4(a[mi][0], a[mi][1], a[mi][2], a[mi][3], ad);
                }
#pragma unroll
                for (int nj = 0; nj < 2; nj++) {
                    uint32_t f0, f1, f2, f3;
                    uint32_t bd = bB + (uint32_t)((wn * 32 + nj * 16) * PB + ks * 32) + laneoffB;
                    ldsm4(f0, f1, f2, f3, bd);
#pragma unroll
                    for (int mi = 0; mi < 2; mi++) {
                        mma_bf16(acc[mi][nj * 2],     a[mi], f0, f2);
                        mma_bf16(acc[mi][nj * 2 + 1], a[mi], f1, f3);
                    }
                }
            }
            // refill consumed buffer (safe: LDSM of chunk c already retired
            // before these cp.async issue, by warp program order)
            if (c + 2 < 16) issueA(c + 2);
        }
        __syncthreads();   // all warps done with A buffers; Gs overlays them

        // ---- stage gate tile (overlays A buffers) — coalesced transpose ----
        float* Gs = (float*)(smem + ABASE);
        const int gid = lane >> 2;
        const int tig = lane & 3;
#pragma unroll
        for (int mi = 0; mi < 2; mi++) {
#pragma unroll
            for (int q = 0; q < 4; q++) {
                int R = wm * 32 + mi * 16 + gid;
                int C = wn * 32 + (q >> 1) * 16 + (q & 1) * 8 + tig * 2;
                float4 v = acc[mi][q];
                Gs[R * GSP + C]           = v.x;
                Gs[R * GSP + C + 1]       = v.y;
                Gs[(R + 8) * GSP + C]     = v.z;
                Gs[(R + 8) * GSP + C + 1] = v.w;
            }
        }
        __syncthreads();

        // ---- fused LSTM cell update (c in registers, coalesced I/O) ----
#pragma unroll
        for (int l = 0; l < 8; l++) {
            int m = l * 16 + mrow;
            float ig = Gs[m * GSP + jj]      + xr[l][0];
            float fg = Gs[m * GSP + 16 + jj] + xr[l][1];
            float gg = Gs[m * GSP + 32 + jj] + xr[l][2];
            float og = Gs[m * GSP + 48 + jj] + xr[l][3];

            float si = sigmoid_fast(ig);
            float sf = sigmoid_fast(fg);
            float so = sigmoid_fast(og);
            float tg = tanh_fast(gg);

            float c2 = sf * cr[l] + si * tg;
            cr[l] = c2;
            hout[(b0 + m) * HID + j0 + jj] = __float2bfloat16(so * tanh_fast(c2));
        }

        if (t + 1 < TT) {
            __syncthreads();               // all hout writes done
            if (tid == 0)
                asm volatile("red.release.gpu.global.add.u32 [%0], 1;"
                             :: "l"(bp) : "memory");
            pre_xg(t + 1);                 // overlaps with other CTAs arriving
            if (tid == 0) {
                unsigned target = 64u * (unsigned)(t + 1);
                unsigned v;
                do {
                    asm volatile("ld.acquire.gpu.global.u32 %0, [%1];"
                                 : "=r"(v) : "l"(bp) : "memory");
                    if (v >= target) break;
                    __nanosleep(32);
                } while (1);
            }
            __syncthreads();
        }
    }
}

// ---------------- final FC + sigmoid (OUT = 1, launch #5) ----------------
__global__ void final_fc(const float* __restrict__ fc_w,
                         const float* __restrict__ fc_b,
                         const __nv_bfloat16* __restrict__ h,
                         float* __restrict__ out)
{
    int bb = blockIdx.x;
    int tid = threadIdx.x;
    float s = 0.f;
    for (int k = tid; k < HID; k += 128)
        s += __bfloat162float(h[bb * HID + k]) * fc_w[k];
    __shared__ float red[128];
    red[tid] = s;
    __syncthreads();
    for (int off = 64; off > 0; off >>= 1) {
        if (tid < off) red[tid] += red[tid + off];
        __syncthreads();
    }
    if (tid == 0)
        out[bb] = 1.f / (1.f + expf(-(red[0] + fc_b[0])));
}

// ---------------- launch ----------------
extern "C" void kernel_launch(void* const* d_in, const int* in_sizes, int n_in,
                              void* d_out, int out_size)
{
    const void*  text = d_in[0];
    const float* emb  = (const float*)d_in[1];
    const float* w_ih = (const float*)d_in[2];
    const float* w_hh = (const float*)d_in[3];
    const float* b_ih = (const float*)d_in[4];
    const float* b_hh = (const float*)d_in[5];
    const float* fc_w = (const float*)d_in[6];
    const float* fc_b = (const float*)d_in[7];
    float* out = (float*)d_out;

    init_all<<<(BB * HID + 255) / 256, 256>>>(text);                   // 1
    conv_all<<<(unsigned)(N4_WHH + N4_WIH + N4_EMB) / 256, 256>>>(w_hh, w_ih, emb); // 2

    dim3 g1(512, 32);
    embed_mma<<<g1, 256>>>(text, b_ih, b_hh);                          // 3

    cudaFuncSetAttribute(lstm_persist, cudaFuncAttributeMaxDynamicSharedMemorySize, SMTOT);
    lstm_persist<<<128, 256, SMTOT>>>();                               // 4  <- ncu capture slot

    __nv_bfloat16* h0;
    cudaGetSymbolAddress((void**)&h0, g_hb);
    final_fc<<<BB, 128>>>(fc_w, fc_b, h0, out);                        // 5
}

// round 15
// speedup vs baseline: 1.5262x; 1.5262x over previous
#include <cuda_runtime.h>
#include <cuda_bf16.h>
#include <cuda_fp16.h>
#include <math.h>
#include <stdint.h>

#define VOCAB 50000
#define EMB   512
#define HID   1024
#define G4    4096   // 4*HID
#define TT    256
#define BB    256

// ---------------- device scratch ----------------
__device__ __half g_xg[(size_t)TT * BB * G4];         // [T][B][4H] input gates (+biases), fp16
__device__ __nv_bfloat16 g_hb[2][BB * HID];           // double-buffered hidden (bf16)
__device__ __nv_bfloat16 g_whh[(size_t)G4 * HID];     // bf16 w_hh
__device__ __nv_bfloat16 g_wih[(size_t)G4 * EMB];     // bf16 w_ih
__device__ __nv_bfloat16 g_emb[(size_t)VOCAB * EMB];  // bf16 embedding table
__device__ int   g_is64;
__device__ unsigned g_bar2[2];                        // per-batch-group barriers

// ---------------- helpers ----------------
__device__ __forceinline__ uint32_t smem_u32(const void* p) {
    uint32_t a;
    asm("{ .reg .u64 t; cvta.to.shared.u64 t, %1; cvt.u32.u64 %0, t; }" : "=r"(a) : "l"(p));
    return a;
}
__device__ __forceinline__ void cpasync16(uint32_t dst, const void* src) {
    asm volatile("cp.async.cg.shared.global [%0], [%1], 16;" :: "r"(dst), "l"(src));
}
#define CP_COMMIT()  asm volatile("cp.async.commit_group;" ::: "memory")
#define CP_WAIT(n)   asm volatile("cp.async.wait_group %0;" :: "n"(n) : "memory")

__device__ __forceinline__ void ldsm4(uint32_t& r0, uint32_t& r1, uint32_t& r2, uint32_t& r3,
                                      uint32_t addr) {
    asm volatile("ldmatrix.sync.aligned.m8n8.x4.shared.b16 {%0,%1,%2,%3}, [%4];"
                 : "=r"(r0), "=r"(r1), "=r"(r2), "=r"(r3) : "r"(addr));
}
__device__ __forceinline__ void mma_bf16(float4& d, const uint32_t a[4],
                                         uint32_t b0, uint32_t b1) {
    asm volatile("mma.sync.aligned.m16n8k16.row.col.f32.bf16.bf16.f32 "
        "{%0,%1,%2,%3}, {%4,%5,%6,%7}, {%8,%9}, {%0,%1,%2,%3};"
        : "+f"(d.x), "+f"(d.y), "+f"(d.z), "+f"(d.w)
        : "r"(a[0]), "r"(a[1]), "r"(a[2]), "r"(a[3]), "r"(b0), "r"(b1));
}

__device__ __forceinline__ float sigmoid_fast(float x) {
    return 1.f / (1.f + __expf(-x));
}
__device__ __forceinline__ float tanh_fast(float x) {
    x = fminf(fmaxf(x, -15.f), 15.f);
    float e = __expf(2.f * x);
    return (e - 1.f) / (e + 1.f);
}

// ---------------- prep kernels ----------------
__global__ void init_all(const void* text) {
    int i = blockIdx.x * blockDim.x + threadIdx.x;
    if (i == 0) {
        const long long* p = (const long long*)text;
        int ok = 1;
        for (int k = 0; k < 64; k++) {
            long long v = p[k];
            if (v < 0 || v >= VOCAB) ok = 0;
        }
        g_is64 = ok;
        g_bar2[0] = 0u;
        g_bar2[1] = 0u;
    }
    if (i < BB * HID) {
        g_hb[0][i] = __float2bfloat16(0.f);
        g_hb[1][i] = __float2bfloat16(0.f);
    }
}

#define N4_WHH  ((size_t)G4 * HID / 4)
#define N4_WIH  ((size_t)G4 * EMB / 4)
#define N4_EMB  ((size_t)VOCAB * EMB / 4)
__global__ void conv_all(const float* __restrict__ whh,
                         const float* __restrict__ wih,
                         const float* __restrict__ emb)
{
    size_t i4 = (size_t)blockIdx.x * 256 + threadIdx.x;
    const float* src;
    __nv_bfloat16* dst;
    size_t k4;
    if (i4 < N4_WHH)                    { src = whh; dst = g_whh; k4 = i4; }
    else if (i4 < N4_WHH + N4_WIH)      { src = wih; dst = g_wih; k4 = i4 - N4_WHH; }
    else                                { src = emb; dst = g_emb; k4 = i4 - N4_WHH - N4_WIH; }
    size_t i = k4 * 4;
    float4 v = *(const float4*)(src + i);
    *(__nv_bfloat162*)(dst + i)     = __floats2bfloat162_rn(v.x, v.y);
    *(__nv_bfloat162*)(dst + i + 2) = __floats2bfloat162_rn(v.z, v.w);
}

// ---------------- bf16 MMA embedding gather + input GEMM (launch #3) ----------------
#define EPITCH 80
#define ESA0   0
#define ESA1   10240
#define ESB0   20480
#define ESB1   30720
#define ESEND  40960

__global__ __launch_bounds__(256) void embed_mma(
    const void* __restrict__ text,
    const float* __restrict__ b_ih,
    const float* __restrict__ b_hh)
{
    __shared__ __align__(16) char smem[ESEND];
    __shared__ int   toks[128];
    __shared__ float bias[128];
    const uint32_t sb = smem_u32(smem);

    const int tid  = threadIdx.x;
    const int lane = tid & 31;
    const int warp = tid >> 5;
    const int wm   = warp >> 1;
    const int wn   = warp & 1;
    const int m0 = blockIdx.x * 128;
    const int n0 = blockIdx.y * 128;

    if (tid < 128) {
        int m = m0 + tid;
        toks[tid] = g_is64 ? (int)((const long long*)text)[m]
                           : ((const int*)text)[m];
        bias[tid] = b_ih[n0 + tid] + b_hh[n0 + tid];
    }
    __syncthreads();

    auto issue = [&](int buf, int chunk) {
        const int k0 = chunk * 32;
#pragma unroll
        for (int l = 0; l < 2; l++) {
            int idx = l * 256 + tid;
            int r = idx >> 2, q = (idx & 3) << 3;
            cpasync16(sb + (buf ? ESA1 : ESA0) + r * EPITCH + q * 2,
                      g_emb + (size_t)toks[r] * EMB + k0 + q);
        }
#pragma unroll
        for (int l = 0; l < 2; l++) {
            int idx = l * 256 + tid;
            int r = idx >> 2, q = (idx & 3) << 3;
            cpasync16(sb + (buf ? ESB1 : ESB0) + r * EPITCH + q * 2,
                      g_wih + (size_t)(n0 + r) * EMB + k0 + q);
        }
        CP_COMMIT();
    };

    float4 acc[2][8];
#pragma unroll
    for (int i = 0; i < 2; i++)
#pragma unroll
        for (int j = 0; j < 8; j++) acc[i][j] = make_float4(0.f, 0.f, 0.f, 0.f);

    issue(0, 0);
    issue(1, 1);

    const uint32_t laneoff = (uint32_t)((lane & 15) * EPITCH + (lane >> 4) * 16);

    for (int c = 0; c < 16; c++) {
        if (c < 15) CP_WAIT(1);
        else        CP_WAIT(0);
        __syncthreads();

        const uint32_t aB = sb + ((c & 1) ? ESA1 : ESA0);
        const uint32_t bB = sb + ((c & 1) ? ESB1 : ESB0);

#pragma unroll
        for (int ks = 0; ks < 2; ks++) {
            uint32_t a[2][4];
#pragma unroll
            for (int mi = 0; mi < 2; mi++) {
                uint32_t ad = aB + (uint32_t)((wm * 32 + mi * 16) * EPITCH + ks * 32) + laneoff;
                ldsm4(a[mi][0], a[mi][1], a[mi][2], a[mi][3], ad);
            }
#pragma unroll
            for (int nj = 0; nj < 4; nj++) {
                uint32_t f0, f1, f2, f3;
                uint32_t bd = bB + (uint32_t)((wn * 64 + nj * 16) * EPITCH + ks * 32) + laneoff;
                ldsm4(f0, f1, f2, f3, bd);
#pragma unroll
                for (int mi = 0; mi < 2; mi++) {
                    mma_bf16(acc[mi][nj * 2],     a[mi], f0, f2);
                    mma_bf16(acc[mi][nj * 2 + 1], a[mi], f1, f3);
                }
            }
        }
        __syncthreads();
        if (c + 2 < 16) issue(c & 1, c + 2);
    }

    const int gid = lane >> 2;
    const int tig = lane & 3;
#pragma unroll
    for (int mi = 0; mi < 2; mi++) {
        int R = wm * 32 + mi * 16 + gid;
        int mA = m0 + R;
        int mB = mA + 8;
        size_t baseA = ((size_t)(mA & 255) * BB + (mA >> 8)) * G4 + n0;
        size_t baseB = ((size_t)(mB & 255) * BB + (mB >> 8)) * G4 + n0;
#pragma unroll
        for (int nj = 0; nj < 4; nj++) {
#pragma unroll
            for (int h = 0; h < 2; h++) {
                float4 v = acc[mi][nj * 2 + h];
                int C = wn * 64 + nj * 16 + h * 8 + tig * 2;
                *(__half2*)(g_xg + baseA + C) =
                    __floats2half2_rn(v.x + bias[C], v.y + bias[C + 1]);
                *(__half2*)(g_xg + baseB + C) =
                    __floats2half2_rn(v.z + bias[C], v.w + bias[C + 1]);
            }
        }
    }
}

// ---------------- persistent recurrent kernel (R10 champion structure) ----------------
#define BM   128
#define BJ   16
#define BK   128
#define PA   272
#define PB   2064
#define SMB  0
#define SMA0 132096
#define SMA1 166912
#define SMTOT 201728
#define GSP  68

__global__ __launch_bounds__(256, 1) void lstm_persist()
{
    extern __shared__ __align__(16) char smem[];
    const uint32_t sb = smem_u32(smem);

    const int tid  = threadIdx.x;
    const int lane = tid & 31;
    const int warp = tid >> 5;
    const int wm   = warp >> 1;          // 0..3
    const int wn   = warp & 1;           // 0..1
    const int cta  = blockIdx.x;
    const int grp  = cta >> 6;           // batch group 0/1
    const int b0   = grp * BM;
    const int j0   = (cta & 63) * BJ;

    // resident w_hh slice: 64 rows x 2048B
#pragma unroll
    for (int l = 0; l < 32; l++) {
        int idx = l * 256 + tid;
        int r = idx >> 7;
        int q = idx & 127;
        int grow = ((r >> 4) << 10) + j0 + (r & 15);
        cpasync16(sb + SMB + r * PB + q * 16, g_whh + (size_t)grow * HID + q * 8);
    }
    CP_COMMIT();
    CP_WAIT(0);
    __syncthreads();

    const uint32_t laneoff  = (uint32_t)((lane & 15) * PA + (lane >> 4) * 16);
    const uint32_t laneoffB = (uint32_t)((lane & 15) * PB + (lane >> 4) * 16);

    // paired-cell epilogue mapping: each thread owns 4 rows x 2 adjacent cols
    const int mrow2 = tid >> 3;          // 0..31 base row offset
    const int jj2   = (tid & 7) * 2;     // even column
    float cr[8];
#pragma unroll
    for (int l = 0; l < 8; l++) cr[l] = 0.f;
    float2 xr[4][4];                     // [row][gate] pairs

    auto pre_xg = [&](int t) {
        const __half* xb = g_xg + ((size_t)t * BB + b0) * G4 + j0 + jj2;
#pragma unroll
        for (int l = 0; l < 4; l++) {
            const __half* p = xb + (size_t)(l * 32 + mrow2) * G4;
            xr[l][0] = __half22float2(*(const __half2*)(p));
            xr[l][1] = __half22float2(*(const __half2*)(p + 1024));
            xr[l][2] = __half22float2(*(const __half2*)(p + 2048));
            xr[l][3] = __half22float2(*(const __half2*)(p + 3072));
        }
    };
    pre_xg(0);

    unsigned* bp = &g_bar2[grp];

    for (int t = 0; t < TT; t++) {
        const __nv_bfloat16* hin = g_hb[t & 1];
        __nv_bfloat16* hout      = g_hb[(t + 1) & 1];

#pragma unroll
        for (int pc = 0; pc < 2; pc++) {
#pragma unroll
            for (int l = 0; l < 8; l++) {
                int idx = l * 256 + tid;
                int r = idx >> 4, q = idx & 15;
                cpasync16(sb + (pc ? SMA1 : SMA0) + r * PA + q * 16,
                          hin + (size_t)(b0 + r) * HID + pc * BK + q * 8);
            }
            CP_COMMIT();
        }

        float4 acc[2][4];
#pragma unroll
        for (int i = 0; i < 2; i++)
#pragma unroll
            for (int j = 0; j < 4; j++) acc[i][j] = make_float4(0.f, 0.f, 0.f, 0.f);

        for (int c = 0; c < 8; c++) {
            if (c < 7) CP_WAIT(1);
            else       CP_WAIT(0);
            __syncthreads();

            const uint32_t aB = sb + ((c & 1) ? SMA1 : SMA0);
            const uint32_t bB = sb + SMB + (uint32_t)(c * 256);

#pragma unroll
            for (int ks = 0; ks < 8; ks++) {
                uint32_t a[2][4];
#pragma unroll
                for (int mi = 0; mi < 2; mi++) {
                    uint32_t ad = aB + (uint32_t)((wm * 32 + mi * 16) * PA + ks * 32) + laneoff;
                    ldsm4(a[mi][0], a[mi][1], a[mi][2], a[mi][3], ad);
                }
#pragma unroll
                for (int nj = 0; nj < 2; nj++) {
                    uint32_t f0, f1, f2, f3;
                    uint32_t bd = bB + (uint32_t)((wn * 32 + nj * 16) * PB + ks * 32) + laneoffB;
                    ldsm4(f0, f1, f2, f3, bd);
#pragma unroll
                    for (int mi = 0; mi < 2; mi++) {
                        mma_bf16(acc[mi][nj * 2],     a[mi], f0, f2);
                        mma_bf16(acc[mi][nj * 2 + 1], a[mi], f1, f3);
                    }
                }
            }
            __syncthreads();
            if (c + 2 < 8) {
#pragma unroll
                for (int l = 0; l < 8; l++) {
                    int idx = l * 256 + tid;
                    int r = idx >> 4, q = idx & 15;
                    cpasync16(sb + ((c & 1) ? SMA1 : SMA0) + r * PA + q * 16,
                              hin + (size_t)(b0 + r) * HID + (c + 2) * BK + q * 8);
                }
                CP_COMMIT();
            }
        }

        // ---- stage gate tile (overlays A0) — coalesced transpose buffer ----
        float* Gs = (float*)(smem + SMA0);
        const int gid = lane >> 2;
        const int tig = lane & 3;
#pragma unroll
        for (int mi = 0; mi < 2; mi++) {
#pragma unroll
            for (int q = 0; q < 4; q++) {
                int R = wm * 32 + mi * 16 + gid;
                int C = wn * 32 + (q >> 1) * 16 + (q & 1) * 8 + tig * 2;
                float4 v = acc[mi][q];
                Gs[R * GSP + C]           = v.x;
                Gs[R * GSP + C + 1]       = v.y;
                Gs[(R + 8) * GSP + C]     = v.z;
                Gs[(R + 8) * GSP + C + 1] = v.w;
            }
        }
        __syncthreads();

        // ---- fused LSTM cell update: 4 rows x 2 cols per thread (paired I/O) ----
#pragma unroll
        for (int l = 0; l < 4; l++) {
            int m = l * 32 + mrow2;
            float2 ig2 = *(const float2*)&Gs[m * GSP + jj2];
            float2 fg2 = *(const float2*)&Gs[m * GSP + 16 + jj2];
            float2 gg2 = *(const float2*)&Gs[m * GSP + 32 + jj2];
            float2 og2 = *(const float2*)&Gs[m * GSP + 48 + jj2];

            float h0v, h1v;
#pragma unroll
            for (int k = 0; k < 2; k++) {
                float ig = (k ? ig2.y : ig2.x) + (k ? xr[l][0].y : xr[l][0].x);
                float fg = (k ? fg2.y : fg2.x) + (k ? xr[l][1].y : xr[l][1].x);
                float gg = (k ? gg2.y : gg2.x) + (k ? xr[l][2].y : xr[l][2].x);
                float og = (k ? og2.y : og2.x) + (k ? xr[l][3].y : xr[l][3].x);

                float si = sigmoid_fast(ig);
                float sf = sigmoid_fast(fg);
                float so = sigmoid_fast(og);
                float tg = tanh_fast(gg);

                float c2 = sf * cr[l * 2 + k] + si * tg;
                cr[l * 2 + k] = c2;
                float hv = so * tanh_fast(c2);
                if (k) h1v = hv; else h0v = hv;
            }
            *(__nv_bfloat162*)(hout + (size_t)(b0 + m) * HID + j0 + jj2) =
                __floats2bfloat162_rn(h0v, h1v);
        }

        if (t + 1 < TT) {
            __syncthreads();               // all hout writes done
            if (tid == 0)
                asm volatile("red.release.gpu.global.add.u32 [%0], 1;"
                             :: "l"(bp) : "memory");
            pre_xg(t + 1);                 // overlaps with other CTAs arriving
            if (tid == 0) {
                unsigned target = 64u * (unsigned)(t + 1);
                unsigned v;
                do {
                    asm volatile("ld.acquire.gpu.global.u32 %0, [%1];"
                                 : "=r"(v) : "l"(bp) : "memory");
                    if (v >= target) break;
                    __nanosleep(32);
                } while (1);
            }
            __syncthreads();
        }
    }
}

// ---------------- final FC + sigmoid (OUT = 1, launch #5) ----------------
__global__ void final_fc(const float* __restrict__ fc_w,
                         const float* __restrict__ fc_b,
                         const __nv_bfloat16* __restrict__ h,
                         float* __restrict__ out)
{
    int bb = blockIdx.x;
    int tid = threadIdx.x;
    float s = 0.f;
    for (int k = tid; k < HID; k += 128)
        s += __bfloat162float(h[bb * HID + k]) * fc_w[k];
    __shared__ float red[128];
    red[tid] = s;
    __syncthreads();
    for (int off = 64; off > 0; off >>= 1) {
        if (tid < off) red[tid] += red[tid + off];
        __syncthreads();
    }
    if (tid == 0)
        out[bb] = 1.f / (1.f + expf(-(red[0] + fc_b[0])));
}

// ---------------- launch ----------------
extern "C" void kernel_launch(void* const* d_in, const int* in_sizes, int n_in,
                              void* d_out, int out_size)
{
    const void*  text = d_in[0];
    const float* emb  = (const float*)d_in[1];
    const float* w_ih = (const float*)d_in[2];
    const float* w_hh = (const float*)d_in[3];
    const float* b_ih = (const float*)d_in[4];
    const float* b_hh = (const float*)d_in[5];
    const float* fc_w = (const float*)d_in[6];
    const float* fc_b = (const float*)d_in[7];
    float* out = (float*)d_out;

    init_all<<<(BB * HID + 255) / 256, 256>>>(text);                   // 1
    conv_all<<<(unsigned)(N4_WHH + N4_WIH + N4_EMB) / 256, 256>>>(w_hh, w_ih, emb); // 2

    dim3 g1(512, 32);
    embed_mma<<<g1, 256>>>(text, b_ih, b_hh);                          // 3

    cudaFuncSetAttribute(lstm_persist, cudaFuncAttributeMaxDynamicSharedMemorySize, SMTOT);
    lstm_persist<<<128, 256, SMTOT>>>();                               // 4  <- ncu capture slot

    __nv_bfloat16* h0;
    cudaGetSymbolAddress((void**)&h0, g_hb);
    final_fc<<<BB, 128>>>(fc_w, fc_b, h0, out);                        // 5
}